// round 1
// baseline (speedup 1.0000x reference)
#include <cuda_runtime.h>
#include <math.h>

#define Nn   4096
#define DIN  512
#define DOUT 256
#define NH   3
#define BN_EPS 1e-5f
#define MAXNBR 512

// ---------------- scratch (device globals; no runtime allocation) ----------
static __device__ float g_proj[NH * Nn * DOUT];   // 12.6 MB
static __device__ float g_ssrc[NH * Nn];
static __device__ float g_stgt[NH * Nn];
static __device__ float g_outpre[Nn * DOUT];      // 4 MB
static __device__ float g_psum[64 * DOUT];
static __device__ float g_psq [64 * DOUT];
static __device__ float g_scale[DOUT];
static __device__ float g_shift[DOUT];

// ---------------- 1) proj[h] = features @ weight[h]  (fp32 SGEMM) ----------
// BM=128, BN=64, BK=16, 256 threads, 8x4 per thread
__global__ __launch_bounds__(256) void proj_gemm(
    const float* __restrict__ F,   // [Nn, DIN]
    const float* __restrict__ W)   // [NH, DIN, DOUT]
{
    const int h  = blockIdx.z;
    const int m0 = blockIdx.x * 128;
    const int n0 = blockIdx.y * 64;
    const int tid = threadIdx.x;

    __shared__ float As[16][128];
    __shared__ float Bs[16][64];

    const int ar = tid >> 2;          // 0..63
    const int ac = (tid & 3) * 4;     // 0,4,8,12
    const int bk = tid >> 4;          // 0..15
    const int bn = (tid & 15) * 4;    // 0..60

    const int tx = tid & 15;          // n-group (4 cols)
    const int ty = tid >> 4;          // m-group (8 rows)

    float acc[8][4];
#pragma unroll
    for (int i = 0; i < 8; i++)
#pragma unroll
        for (int j = 0; j < 4; j++) acc[i][j] = 0.f;

    for (int k0 = 0; k0 < DIN; k0 += 16) {
        // load A tile: 128x16
#pragma unroll
        for (int rr = 0; rr < 2; rr++) {
            int r = ar + rr * 64;
            float4 v = *(const float4*)&F[(size_t)(m0 + r) * DIN + k0 + ac];
            As[ac + 0][r] = v.x;
            As[ac + 1][r] = v.y;
            As[ac + 2][r] = v.z;
            As[ac + 3][r] = v.w;
        }
        // load B tile: 16x64
        {
            float4 v = *(const float4*)&W[((size_t)h * DIN + k0 + bk) * DOUT + n0 + bn];
            *(float4*)&Bs[bk][bn] = v;
        }
        __syncthreads();

#pragma unroll
        for (int k = 0; k < 16; k++) {
            float a[8], b[4];
#pragma unroll
            for (int i = 0; i < 8; i++) a[i] = As[k][ty * 8 + i];
#pragma unroll
            for (int j = 0; j < 4; j++) b[j] = Bs[k][tx * 4 + j];
#pragma unroll
            for (int i = 0; i < 8; i++)
#pragma unroll
                for (int j = 0; j < 4; j++) acc[i][j] = fmaf(a[i], b[j], acc[i][j]);
        }
        __syncthreads();
    }

#pragma unroll
    for (int i = 0; i < 8; i++) {
        float4 o;
        o.x = acc[i][0]; o.y = acc[i][1]; o.z = acc[i][2]; o.w = acc[i][3];
        *(float4*)&g_proj[((size_t)h * Nn + m0 + ty * 8 + i) * DOUT + n0 + tx * 4] = o;
    }
}

// ---------------- 2) attention logit scalars ------------------------------
// one warp per (h,n): s_src[h,n] = <proj[h,n,:], score_src[h,:]>, same for tgt
__global__ __launch_bounds__(256) void score_kernel(
    const float* __restrict__ Ssrc,   // [NH, DOUT]
    const float* __restrict__ Stgt)   // [NH, DOUT]
{
    int gw   = (blockIdx.x * blockDim.x + threadIdx.x) >> 5;
    int lane = threadIdx.x & 31;
    if (gw >= NH * Nn) return;
    int h = gw / Nn, n = gw % Nn;
    const float* row = g_proj + ((size_t)h * Nn + n) * DOUT;
    float a = 0.f, b = 0.f;
#pragma unroll
    for (int o = lane; o < DOUT; o += 32) {
        float p = row[o];
        a = fmaf(p, Ssrc[h * DOUT + o], a);
        b = fmaf(p, Stgt[h * DOUT + o], b);
    }
#pragma unroll
    for (int s = 16; s > 0; s >>= 1) {
        a += __shfl_xor_sync(0xffffffffu, a, s);
        b += __shfl_xor_sync(0xffffffffu, b, s);
    }
    if (lane == 0) {
        g_ssrc[h * Nn + n] = a;
        g_stgt[h * Nn + n] = b;
    }
}

// ---------------- 3) sparse attention + head-mean + bias -------------------
// one block (256 threads) per destination row i; thread t owns output col t
__global__ __launch_bounds__(256) void attn_kernel(
    const float* __restrict__ adj,    // [Nn, Nn]
    const float* __restrict__ bias)   // [DOUT]
{
    const int i   = blockIdx.x;
    const int tid = threadIdx.x;

    __shared__ int   s_cnt;
    __shared__ int   s_idx[MAXNBR];
    __shared__ float s_a  [MAXNBR];
    __shared__ float s_w  [MAXNBR];
    __shared__ float red  [256];

    if (tid == 0) s_cnt = 0;
    __syncthreads();

    // gather nonzero adjacency entries of row i
    const float* arow = adj + (size_t)i * Nn;
    for (int j = tid; j < Nn; j += 256) {
        float a = arow[j];
        if (a != 0.f) {
            int p = atomicAdd(&s_cnt, 1);
            if (p < MAXNBR) { s_idx[p] = j; s_a[p] = a; }
        }
    }
    __syncthreads();
    const int cnt = min(s_cnt, MAXNBR);

    float total = 0.f;

    for (int h = 0; h < NH; h++) {
        const float srci = g_ssrc[h * Nn + i];
        // logits
        for (int k = tid; k < cnt; k += 256) {
            float x = srci + g_stgt[h * Nn + s_idx[k]];
            float l = (x > 0.f) ? x : 0.2f * x;   // leaky_relu 0.2
            s_w[k] = l + s_a[k];                   // + conn (edge weight)
        }
        __syncthreads();

        // max-reduce
        float m = -3.4e38f;
        for (int k = tid; k < cnt; k += 256) m = fmaxf(m, s_w[k]);
        red[tid] = m;
        __syncthreads();
#pragma unroll
        for (int s = 128; s > 0; s >>= 1) {
            if (tid < s) red[tid] = fmaxf(red[tid], red[tid + s]);
            __syncthreads();
        }
        const float mx = red[0];
        __syncthreads();

        // exp + sum-reduce
        float sm = 0.f;
        for (int k = tid; k < cnt; k += 256) {
            float e = expf(s_w[k] - mx);
            s_w[k] = e;
            sm += e;
        }
        red[tid] = sm;
        __syncthreads();
#pragma unroll
        for (int s = 128; s > 0; s >>= 1) {
            if (tid < s) red[tid] += red[tid + s];
            __syncthreads();
        }
        const float inv = 1.f / red[0];
        __syncthreads();

        // weighted gather of proj rows (thread t owns column t)
        const float* base = g_proj + (size_t)h * Nn * DOUT;
        float acc = 0.f;
        int k = 0;
        for (; k + 4 <= cnt; k += 4) {
            float w0 = s_w[k], w1 = s_w[k + 1], w2 = s_w[k + 2], w3 = s_w[k + 3];
            int   j0 = s_idx[k], j1 = s_idx[k + 1], j2 = s_idx[k + 2], j3 = s_idx[k + 3];
            float p0 = base[(size_t)j0 * DOUT + tid];
            float p1 = base[(size_t)j1 * DOUT + tid];
            float p2 = base[(size_t)j2 * DOUT + tid];
            float p3 = base[(size_t)j3 * DOUT + tid];
            acc = fmaf(w0, p0, acc);
            acc = fmaf(w1, p1, acc);
            acc = fmaf(w2, p2, acc);
            acc = fmaf(w3, p3, acc);
        }
        for (; k < cnt; k++)
            acc = fmaf(s_w[k], base[(size_t)s_idx[k] * DOUT + tid], acc);

        total += acc * inv;
        __syncthreads();   // protect s_w before next head
    }

    g_outpre[(size_t)i * DOUT + tid] = total * (1.f / 3.f) + bias[tid];
}

// ---------------- 4) batchnorm stats + apply + relu ------------------------
__global__ __launch_bounds__(256) void bn_partial() {
    int c = threadIdx.x;
    int r0 = blockIdx.x * 64;
    float s = 0.f, q = 0.f;
    for (int r = r0; r < r0 + 64; r++) {
        float v = g_outpre[(size_t)r * DOUT + c];
        s += v;
        q = fmaf(v, v, q);
    }
    g_psum[blockIdx.x * DOUT + c] = s;
    g_psq [blockIdx.x * DOUT + c] = q;
}

__global__ __launch_bounds__(256) void bn_stats(
    const float* __restrict__ gamma, const float* __restrict__ beta)
{
    int c = threadIdx.x;
    float s = 0.f, q = 0.f;
    for (int b = 0; b < 64; b++) {
        s += g_psum[b * DOUT + c];
        q += g_psq [b * DOUT + c];
    }
    float mu  = s * (1.f / Nn);
    float var = q * (1.f / Nn) - mu * mu;
    float sc  = gamma[c] * rsqrtf(var + BN_EPS);
    g_scale[c] = sc;
    g_shift[c] = beta[c] - mu * sc;
}

__global__ __launch_bounds__(256) void bn_apply(float* __restrict__ out) {
    int c = threadIdx.x;
    size_t idx = (size_t)blockIdx.x * DOUT + c;
    float v = g_outpre[idx] * g_scale[c] + g_shift[c];
    out[idx] = fmaxf(v, 0.f);
}

// ---------------- launch ----------------------------------------------------
extern "C" void kernel_launch(void* const* d_in, const int* in_sizes, int n_in,
                              void* d_out, int out_size)
{
    const float* features  = (const float*)d_in[0]; // [4096,512]
    const float* adj       = (const float*)d_in[1]; // [4096,4096]
    const float* weight    = (const float*)d_in[2]; // [3,512,256]
    const float* bias      = (const float*)d_in[3]; // [256]
    const float* score_src = (const float*)d_in[4]; // [3,256,1]
    const float* score_tgt = (const float*)d_in[5]; // [3,256,1]
    const float* bn_gamma  = (const float*)d_in[6]; // [256]
    const float* bn_beta   = (const float*)d_in[7]; // [256]
    float* out = (float*)d_out;                     // [4096,256]

    dim3 gemm_grid(Nn / 128, DOUT / 64, NH);
    proj_gemm<<<gemm_grid, 256>>>(features, weight);

    int warps = NH * Nn;
    score_kernel<<<(warps * 32 + 255) / 256, 256>>>(score_src, score_tgt);

    attn_kernel<<<Nn, 256>>>(adj, bias);

    bn_partial<<<64, 256>>>();
    bn_stats<<<1, 256>>>(bn_gamma, bn_beta);
    bn_apply<<<Nn, 256>>>(out);
}

// round 2
// speedup vs baseline: 1.3408x; 1.3408x over previous
#include <cuda_runtime.h>
#include <math.h>
#include <stdint.h>

#define Nn   4096
#define DIN  512
#define DOUT 256
#define NH   3
#define BN_EPS 1e-5f
#define MAXNBR 512

// GEMM tiling
#define BM 128
#define BNT 128
#define BK 16

// ---------------- scratch (device globals; no runtime allocation) ----------
static __device__ float g_proj[NH * Nn * DOUT];   // 12.6 MB
static __device__ float g_ssrc[NH * Nn];
static __device__ float g_stgt[NH * Nn];
static __device__ float g_outpre[Nn * DOUT];      // 4 MB
static __device__ float g_psum[256 * DOUT];
static __device__ float g_psq [256 * DOUT];
static __device__ float g_scale[DOUT];
static __device__ float g_shift[DOUT];

// ---------------- tf32 helpers ---------------------------------------------
__device__ __forceinline__ float to_tf32(float x) {
    uint32_t u;
    asm("cvt.rna.tf32.f32 %0, %1;" : "=r"(u) : "f"(x));
    return __uint_as_float(u);
}

__device__ __forceinline__ void mma_tf32(float* d, const uint32_t* a, const uint32_t* b) {
    asm volatile(
        "mma.sync.aligned.m16n8k8.row.col.f32.tf32.tf32.f32 "
        "{%0,%1,%2,%3}, {%4,%5,%6,%7}, {%8,%9}, {%0,%1,%2,%3};"
        : "+f"(d[0]), "+f"(d[1]), "+f"(d[2]), "+f"(d[3])
        : "r"(a[0]), "r"(a[1]), "r"(a[2]), "r"(a[3]),
          "r"(b[0]), "r"(b[1]));
}

// ---------------- 1) proj[h] = features @ weight[h]  (TF32 tensor cores) ---
// 128x128x16 tiles, 256 threads (8 warps in 4x2), double-buffered smem.
__global__ __launch_bounds__(256) void proj_gemm(
    const float* __restrict__ F,   // [Nn, DIN] row-major
    const float* __restrict__ W)   // [NH, DIN, DOUT]
{
    __shared__ float As[2][BM][20];    // [m][k], pad 20 -> conflict-free frag loads
    __shared__ float Bs[2][BK][136];   // [k][n], stride 136 -> conflict-free

    const int h  = blockIdx.z;
    const int m0 = blockIdx.x * BM;
    const int n0 = blockIdx.y * BNT;
    const int tid  = threadIdx.x;
    const int warp = tid >> 5;
    const int lane = tid & 31;
    const int g = lane >> 2;   // groupID 0..7
    const int q = lane & 3;    // threadID in group
    const int wm = warp & 3;   // warp row  (4)
    const int wn = warp >> 2;  // warp col  (2)

    // tile loader indexing
    const int row_a = tid >> 2;          // 0..63 (x2 rows)
    const int kq_a  = (tid & 3) * 4;     // 0,4,8,12
    const int krow_b = tid >> 5;         // 0..7 (x2 rows)
    const int ncol_b = (tid & 31) * 4;   // 0..124

    float acc[2][8][4];
#pragma unroll
    for (int mt = 0; mt < 2; mt++)
#pragma unroll
        for (int nt = 0; nt < 8; nt++)
#pragma unroll
            for (int v = 0; v < 4; v++) acc[mt][nt][v] = 0.f;

    float4 ra0, ra1, rb0, rb1;

#define LDG_TILE(k0)                                                              \
    do {                                                                          \
        ra0 = *(const float4*)&F[(size_t)(m0 + row_a)      * DIN + (k0) + kq_a];  \
        ra1 = *(const float4*)&F[(size_t)(m0 + row_a + 64) * DIN + (k0) + kq_a];  \
        rb0 = *(const float4*)&W[((size_t)h * DIN + (k0) + krow_b)     * DOUT + n0 + ncol_b]; \
        rb1 = *(const float4*)&W[((size_t)h * DIN + (k0) + krow_b + 8) * DOUT + n0 + ncol_b]; \
    } while (0)

#define STS_TILE(buf)                                                             \
    do {                                                                          \
        float4 t;                                                                 \
        t.x = to_tf32(ra0.x); t.y = to_tf32(ra0.y); t.z = to_tf32(ra0.z); t.w = to_tf32(ra0.w); \
        *(float4*)&As[buf][row_a][kq_a] = t;                                      \
        t.x = to_tf32(ra1.x); t.y = to_tf32(ra1.y); t.z = to_tf32(ra1.z); t.w = to_tf32(ra1.w); \
        *(float4*)&As[buf][row_a + 64][kq_a] = t;                                 \
        t.x = to_tf32(rb0.x); t.y = to_tf32(rb0.y); t.z = to_tf32(rb0.z); t.w = to_tf32(rb0.w); \
        *(float4*)&Bs[buf][krow_b][ncol_b] = t;                                   \
        t.x = to_tf32(rb1.x); t.y = to_tf32(rb1.y); t.z = to_tf32(rb1.z); t.w = to_tf32(rb1.w); \
        *(float4*)&Bs[buf][krow_b + 8][ncol_b] = t;                               \
    } while (0)

#define MMA_STEP(buf)                                                             \
    do {                                                                          \
        _Pragma("unroll")                                                         \
        for (int ks = 0; ks < 2; ks++) {                                          \
            const int kb = ks * 8;                                                \
            uint32_t af[2][4];                                                    \
            _Pragma("unroll")                                                     \
            for (int mt = 0; mt < 2; mt++) {                                      \
                const int r = wm * 32 + mt * 16 + g;                              \
                af[mt][0] = __float_as_uint(As[buf][r    ][kb + q    ]);          \
                af[mt][1] = __float_as_uint(As[buf][r + 8][kb + q    ]);          \
                af[mt][2] = __float_as_uint(As[buf][r    ][kb + q + 4]);          \
                af[mt][3] = __float_as_uint(As[buf][r + 8][kb + q + 4]);          \
            }                                                                     \
            uint32_t bf[8][2];                                                    \
            _Pragma("unroll")                                                     \
            for (int nt = 0; nt < 8; nt++) {                                      \
                const int c = wn * 64 + nt * 8 + g;                               \
                bf[nt][0] = __float_as_uint(Bs[buf][kb + q    ][c]);              \
                bf[nt][1] = __float_as_uint(Bs[buf][kb + q + 4][c]);              \
            }                                                                     \
            _Pragma("unroll")                                                     \
            for (int mt = 0; mt < 2; mt++)                                        \
                _Pragma("unroll")                                                 \
                for (int nt = 0; nt < 8; nt++)                                    \
                    mma_tf32(acc[mt][nt], af[mt], bf[nt]);                        \
        }                                                                         \
    } while (0)

    LDG_TILE(0);
    STS_TILE(0);
    __syncthreads();

    int buf = 0;
    const int nIter = DIN / BK;   // 32
    for (int it = 0; it < nIter; it++) {
        if (it + 1 < nIter) LDG_TILE((it + 1) * BK);
        MMA_STEP(buf);
        if (it + 1 < nIter) {
            STS_TILE(buf ^ 1);
            __syncthreads();
            buf ^= 1;
        }
    }

    // epilogue: write fp32 result
#pragma unroll
    for (int mt = 0; mt < 2; mt++) {
        const int r = m0 + wm * 32 + mt * 16 + g;
#pragma unroll
        for (int nt = 0; nt < 8; nt++) {
            const int c = n0 + wn * 64 + nt * 8 + q * 2;
            float2 v0; v0.x = acc[mt][nt][0]; v0.y = acc[mt][nt][1];
            float2 v1; v1.x = acc[mt][nt][2]; v1.y = acc[mt][nt][3];
            *(float2*)&g_proj[((size_t)h * Nn + r    ) * DOUT + c] = v0;
            *(float2*)&g_proj[((size_t)h * Nn + r + 8) * DOUT + c] = v1;
        }
    }
#undef LDG_TILE
#undef STS_TILE
#undef MMA_STEP
}

// ---------------- 2) attention logit scalars ------------------------------
__global__ __launch_bounds__(256) void score_kernel(
    const float* __restrict__ Ssrc,   // [NH, DOUT]
    const float* __restrict__ Stgt)   // [NH, DOUT]
{
    int gw   = (blockIdx.x * blockDim.x + threadIdx.x) >> 5;
    int lane = threadIdx.x & 31;
    if (gw >= NH * Nn) return;
    int h = gw / Nn, n = gw % Nn;
    const float* row = g_proj + ((size_t)h * Nn + n) * DOUT;
    float a = 0.f, b = 0.f;
#pragma unroll
    for (int o = lane; o < DOUT; o += 32) {
        float p = row[o];
        a = fmaf(p, Ssrc[h * DOUT + o], a);
        b = fmaf(p, Stgt[h * DOUT + o], b);
    }
#pragma unroll
    for (int s = 16; s > 0; s >>= 1) {
        a += __shfl_xor_sync(0xffffffffu, a, s);
        b += __shfl_xor_sync(0xffffffffu, b, s);
    }
    if (lane == 0) {
        g_ssrc[h * Nn + n] = a;
        g_stgt[h * Nn + n] = b;
    }
}

// ---------------- 3) sparse attention + head-mean + bias -------------------
__global__ __launch_bounds__(256) void attn_kernel(
    const float* __restrict__ adj,    // [Nn, Nn]
    const float* __restrict__ bias)   // [DOUT]
{
    const int i   = blockIdx.x;
    const int tid = threadIdx.x;

    __shared__ int   s_cnt;
    __shared__ int   s_idx[MAXNBR];
    __shared__ float s_a  [MAXNBR];
    __shared__ float s_w  [MAXNBR];
    __shared__ float red  [256];

    if (tid == 0) s_cnt = 0;
    __syncthreads();

    const float* arow = adj + (size_t)i * Nn;
    for (int j = tid; j < Nn; j += 256) {
        float a = arow[j];
        if (a != 0.f) {
            int p = atomicAdd(&s_cnt, 1);
            if (p < MAXNBR) { s_idx[p] = j; s_a[p] = a; }
        }
    }
    __syncthreads();
    const int cnt = min(s_cnt, MAXNBR);

    float total = 0.f;

    for (int h = 0; h < NH; h++) {
        const float srci = g_ssrc[h * Nn + i];
        for (int k = tid; k < cnt; k += 256) {
            float x = srci + g_stgt[h * Nn + s_idx[k]];
            float l = (x > 0.f) ? x : 0.2f * x;
            s_w[k] = l + s_a[k];
        }
        __syncthreads();

        float m = -3.4e38f;
        for (int k = tid; k < cnt; k += 256) m = fmaxf(m, s_w[k]);
        red[tid] = m;
        __syncthreads();
#pragma unroll
        for (int s = 128; s > 0; s >>= 1) {
            if (tid < s) red[tid] = fmaxf(red[tid], red[tid + s]);
            __syncthreads();
        }
        const float mx = red[0];
        __syncthreads();

        float sm = 0.f;
        for (int k = tid; k < cnt; k += 256) {
            float e = expf(s_w[k] - mx);
            s_w[k] = e;
            sm += e;
        }
        red[tid] = sm;
        __syncthreads();
#pragma unroll
        for (int s = 128; s > 0; s >>= 1) {
            if (tid < s) red[tid] += red[tid + s];
            __syncthreads();
        }
        const float inv = 1.f / red[0];
        __syncthreads();

        const float* base = g_proj + (size_t)h * Nn * DOUT;
        float acc = 0.f;
        int k = 0;
        for (; k + 4 <= cnt; k += 4) {
            float w0 = s_w[k], w1 = s_w[k + 1], w2 = s_w[k + 2], w3 = s_w[k + 3];
            int   j0 = s_idx[k], j1 = s_idx[k + 1], j2 = s_idx[k + 2], j3 = s_idx[k + 3];
            float p0 = base[(size_t)j0 * DOUT + tid];
            float p1 = base[(size_t)j1 * DOUT + tid];
            float p2 = base[(size_t)j2 * DOUT + tid];
            float p3 = base[(size_t)j3 * DOUT + tid];
            acc = fmaf(w0, p0, acc);
            acc = fmaf(w1, p1, acc);
            acc = fmaf(w2, p2, acc);
            acc = fmaf(w3, p3, acc);
        }
        for (; k < cnt; k++)
            acc = fmaf(s_w[k], base[(size_t)s_idx[k] * DOUT + tid], acc);

        total += acc * inv;
        __syncthreads();
    }

    g_outpre[(size_t)i * DOUT + tid] = total * (1.f / 3.f) + bias[tid];
}

// ---------------- 4) batchnorm stats + apply + relu ------------------------
__global__ __launch_bounds__(256) void bn_partial() {
    int c = threadIdx.x;
    int r0 = blockIdx.x * 16;
    float s = 0.f, qq = 0.f;
#pragma unroll
    for (int r = r0; r < r0 + 16; r++) {
        float v = g_outpre[(size_t)r * DOUT + c];
        s += v;
        qq = fmaf(v, v, qq);
    }
    g_psum[blockIdx.x * DOUT + c] = s;
    g_psq [blockIdx.x * DOUT + c] = qq;
}

__global__ __launch_bounds__(256) void bn_stats(
    const float* __restrict__ gamma, const float* __restrict__ beta)
{
    int c = threadIdx.x;
    float s = 0.f, qq = 0.f;
#pragma unroll 8
    for (int b = 0; b < 256; b++) {
        s  += g_psum[b * DOUT + c];
        qq += g_psq [b * DOUT + c];
    }
    float mu  = s * (1.f / Nn);
    float var = qq * (1.f / Nn) - mu * mu;
    float sc  = gamma[c] * rsqrtf(var + BN_EPS);
    g_scale[c] = sc;
    g_shift[c] = beta[c] - mu * sc;
}

__global__ __launch_bounds__(256) void bn_apply(float* __restrict__ out) {
    int c = threadIdx.x;
    size_t idx = (size_t)blockIdx.x * DOUT + c;
    float v = g_outpre[idx] * g_scale[c] + g_shift[c];
    out[idx] = fmaxf(v, 0.f);
}

// ---------------- launch ----------------------------------------------------
extern "C" void kernel_launch(void* const* d_in, const int* in_sizes, int n_in,
                              void* d_out, int out_size)
{
    const float* features  = (const float*)d_in[0]; // [4096,512]
    const float* adj       = (const float*)d_in[1]; // [4096,4096]
    const float* weight    = (const float*)d_in[2]; // [3,512,256]
    const float* bias      = (const float*)d_in[3]; // [256]
    const float* score_src = (const float*)d_in[4]; // [3,256,1]
    const float* score_tgt = (const float*)d_in[5]; // [3,256,1]
    const float* bn_gamma  = (const float*)d_in[6]; // [256]
    const float* bn_beta   = (const float*)d_in[7]; // [256]
    float* out = (float*)d_out;                     // [4096,256]

    dim3 gemm_grid(Nn / BM, DOUT / BNT, NH);        // 32 x 2 x 3
    proj_gemm<<<gemm_grid, 256>>>(features, weight);

    int warps = NH * Nn;
    score_kernel<<<(warps * 32 + 255) / 256, 256>>>(score_src, score_tgt);

    attn_kernel<<<Nn, 256>>>(adj, bias);

    bn_partial<<<256, 256>>>();
    bn_stats<<<1, 256>>>(bn_gamma, bn_beta);
    bn_apply<<<Nn, 256>>>(out);
}